// round 14
// baseline (speedup 1.0000x reference)
#include <cuda_runtime.h>
#include <cuda_bf16.h>
#include <cuda_fp16.h>
#include <math.h>

#define N_NODES 40000
#define N_EDGES 640000
#define HID     128
#define NH      (N_NODES * HID)
#define NPAD    40960   // padded count array (160 blocks * 256)
#define NSCB    160     // scan blocks
#define WPK     64      // u32 per row in presplit arrays (128 k / 2)

// ---------------- device scratch (no allocations allowed) ----------------
__device__ __align__(16) float  g_xproj[NH];
__device__ __align__(16) float  g_state[NH];
__device__ __align__(16) __half g_stateH[NH];     // fp16 gather copy
__device__ __align__(16) unsigned g_aggrhi[N_NODES * WPK];
__device__ __align__(16) unsigned g_aggrlo[N_NODES * WPK];
__device__ __align__(16) unsigned g_whi[HID * WPK];
__device__ __align__(16) unsigned g_wlo[HID * WPK];
__device__ int   g_rowptr[N_NODES + 1];
__device__ int   g_cursor[N_NODES];
__device__ __align__(16) int g_counts[NPAD];
__device__ int   g_col[N_EDGES];
__device__ int   g_bsum[NSCB];
__device__ int   g_boff[NSCB];
__device__ int   g_is64;

// ---------------- bf16 split + mma + ldmatrix helpers ----------------
__device__ __forceinline__ void split_pair(float x, float y,
                                           unsigned& hi, unsigned& lo) {
    __nv_bfloat16 hx = __float2bfloat16_rn(x);
    __nv_bfloat16 hy = __float2bfloat16_rn(y);
    __nv_bfloat16 lx = __float2bfloat16_rn(x - __bfloat162float(hx));
    __nv_bfloat16 ly = __float2bfloat16_rn(y - __bfloat162float(hy));
    hi = (unsigned)__bfloat16_as_ushort(hx) |
         ((unsigned)__bfloat16_as_ushort(hy) << 16);
    lo = (unsigned)__bfloat16_as_ushort(lx) |
         ((unsigned)__bfloat16_as_ushort(ly) << 16);
}

__device__ __forceinline__ void mma_bf16(
    float& c0, float& c1, float& c2, float& c3,
    unsigned a0, unsigned a1, unsigned a2, unsigned a3,
    unsigned b0, unsigned b1)
{
    asm("mma.sync.aligned.m16n8k16.row.col.f32.bf16.bf16.f32 "
        "{%0,%1,%2,%3}, {%4,%5,%6,%7}, {%8,%9}, {%0,%1,%2,%3};"
        : "+f"(c0), "+f"(c1), "+f"(c2), "+f"(c3)
        : "r"(a0), "r"(a1), "r"(a2), "r"(a3), "r"(b0), "r"(b1));
}

__device__ __forceinline__ void ldsm_x4(unsigned r[4], unsigned addr) {
    asm volatile("ldmatrix.sync.aligned.m8n8.x4.shared.b16 {%0,%1,%2,%3}, [%4];"
        : "=r"(r[0]), "=r"(r[1]), "=r"(r[2]), "=r"(r[3]) : "r"(addr));
}
__device__ __forceinline__ void ldsm_x2(unsigned& r0, unsigned& r1, unsigned addr) {
    asm volatile("ldmatrix.sync.aligned.m8n8.x2.shared.b16 {%0,%1}, [%2];"
        : "=r"(r0), "=r"(r1) : "r"(addr));
}

// ---------------- edge dtype probe: int64 vs int32 ----------------
__global__ void detect_kernel(const void* ei) {
    if (threadIdx.x == 0 && blockIdx.x == 0) {
        const long long* p = (const long long*)ei;
        int ok64 = 1;
        for (int i = 0; i < 64; i++) {
            long long v = p[(i * 9973) % 640000];
            if (v < 0 || v >= N_NODES) { ok64 = 0; break; }
        }
        g_is64 = ok64;
    }
}

__device__ __forceinline__ int edge_val(const void* ei, int idx) {
    int v;
    if (g_is64) v = (int)((const long long*)ei)[idx];
    else        v = ((const int*)ei)[idx];
    return ((unsigned)v < N_NODES) ? v : 0;   // clamp: never trap
}

// ---------------- weight pre-split ----------------
__global__ void split_w_kernel(const float* __restrict__ w, int transpose) {
    int idx = blockIdx.x * blockDim.x + threadIdx.x;   // 0..8191
    if (idx >= HID * WPK) return;
    int n = idx >> 6, k2 = idx & 63;
    int k = k2 * 2;
    float a = transpose ? w[k * HID + n]       : w[n * HID + k];
    float b = transpose ? w[(k + 1) * HID + n] : w[n * HID + k + 1];
    unsigned hi, lo;
    split_pair(a, b, hi, lo);
    g_whi[idx] = hi;
    g_wlo[idx] = lo;
}

// ---------------- CSR build ----------------
__global__ void zero_counts_kernel() {
    for (int i = blockIdx.x * blockDim.x + threadIdx.x; i < NPAD;
         i += gridDim.x * blockDim.x)
        g_counts[i] = 0;
}

__global__ void hist_kernel(const void* __restrict__ ei) {
    int e = blockIdx.x * blockDim.x + threadIdx.x;
    if (e < N_EDGES) {
        int dst = edge_val(ei, N_EDGES + e);
        atomicAdd(&g_counts[dst], 1);
    }
}

__global__ void scan_a_kernel() {
    __shared__ int ws[8];
    int t = threadIdx.x, lane = t & 31, wid = t >> 5;
    int v = g_counts[blockIdx.x * 256 + t];
    int s = v;
    for (int o = 16; o > 0; o >>= 1) s += __shfl_down_sync(0xffffffffu, s, o);
    if (lane == 0) ws[wid] = s;
    __syncthreads();
    if (t == 0) {
        int tot = 0;
        for (int i = 0; i < 8; i++) tot += ws[i];
        g_bsum[blockIdx.x] = tot;
    }
}

__global__ void scan_b_kernel() {
    __shared__ int woff[8];
    int t = threadIdx.x, lane = t & 31, wid = t >> 5;
    int v = (t < NSCB) ? g_bsum[t] : 0;
    int p = v;
    for (int o = 1; o < 32; o <<= 1) {
        int n = __shfl_up_sync(0xffffffffu, p, o);
        if (lane >= o) p += n;
    }
    if (lane == 31) woff[wid] = p;
    __syncthreads();
    if (wid == 0) {
        int w = (lane < 8) ? woff[lane] : 0;
        int q = w;
        for (int o = 1; o < 8; o <<= 1) {
            int n = __shfl_up_sync(0xffffffffu, q, o);
            if (lane >= o) q += n;
        }
        if (lane < 8) woff[lane] = q - w;
    }
    __syncthreads();
    if (t < NSCB) g_boff[t] = woff[wid] + (p - v);
}

__global__ void scan_c_kernel() {
    __shared__ int woff[8];
    int t = threadIdx.x, lane = t & 31, wid = t >> 5;
    int i = blockIdx.x * 256 + t;
    int v = g_counts[i];
    int p = v;
    for (int o = 1; o < 32; o <<= 1) {
        int n = __shfl_up_sync(0xffffffffu, p, o);
        if (lane >= o) p += n;
    }
    if (lane == 31) woff[wid] = p;
    __syncthreads();
    if (wid == 0) {
        int w = (lane < 8) ? woff[lane] : 0;
        int q = w;
        for (int o = 1; o < 8; o <<= 1) {
            int n = __shfl_up_sync(0xffffffffu, q, o);
            if (lane >= o) q += n;
        }
        if (lane < 8) woff[lane] = q - w;
    }
    __syncthreads();
    int excl = g_boff[blockIdx.x] + woff[wid] + (p - v);
    if (i < N_NODES) {
        g_cursor[i] = excl;
        g_rowptr[i + 1] = excl + v;
    }
    if (i == 0) g_rowptr[0] = 0;
}

__global__ void fill_kernel(const void* __restrict__ ei) {
    int e = blockIdx.x * blockDim.x + threadIdx.x;
    if (e < N_EDGES) {
        int src = edge_val(ei, e);
        int dst = edge_val(ei, N_EDGES + e);
        int pos = atomicAdd(&g_cursor[dst], 1);
        if ((unsigned)pos < N_EDGES) g_col[pos] = src;
    }
}

// ---------------- edge aggregation: warp/node, fp16 gather, fp32 accum -------
__global__ void __launch_bounds__(256) aggregate_kernel() {
    int node = blockIdx.x * 8 + (threadIdx.x >> 5);
    if (node >= N_NODES) return;
    int lane = threadIdx.x & 31;
    int s = g_rowptr[node];
    int e = g_rowptr[node + 1];
    const uint2* st = (const uint2*)g_stateH;    // 32 uint2 (=4 halves) per node
    float4 acc = make_float4(0.f, 0.f, 0.f, 0.f);
    for (int i = s; i < e; i++) {
        uint2 u = st[g_col[i] * 32 + lane];
        __half2 h01 = *(__half2*)&u.x;
        __half2 h23 = *(__half2*)&u.y;
        float2 f01 = __half22float2(h01);
        float2 f23 = __half22float2(h23);
        acc.x += f01.x; acc.y += f01.y; acc.z += f23.x; acc.w += f23.y;
    }
    unsigned h0, l0, h1, l1;
    split_pair(acc.x, acc.y, h0, l0);
    split_pair(acc.z, acc.w, h1, l1);
    int base = node * WPK + lane * 2;
    *(uint2*)&g_aggrhi[base] = make_uint2(h0, h1);
    *(uint2*)&g_aggrlo[base] = make_uint2(l0, l1);
}

// ---------------- first state update: state = tanh(xproj), + fp16 copy --------
__global__ void tanh_kernel() {
    int i = blockIdx.x * blockDim.x + threadIdx.x;
    if (i < NH) {
        float v = tanhf(g_xproj[i]);
        g_state[i]  = v;
        g_stateH[i] = __float2half(v);
    }
}

// ---------------- bf16-split tensor-core GEMM (pipeline + ldmatrix) ----------
// dst[m][n] = f((bias? xproj) + sum_k A[m][k] * W[n][k])
// A@W ~= Ahi@Whi + Ahi@Wlo + Alo@Whi  (fp32 accum, mma.m16n8k16.bf16)
// 256 threads (8 warps), block tile 64(m) x 128(n), warp tile m32 x n32.
#define GR 64
#define KT 32
#define PU 20    // u32 per smem row; rows at pitch 20 tile all 32 banks for LDSM

// a_sel: 0 = Aext(fp32), 1 = g_state(fp32), 2 = presplit g_aggrhi/lo
// dst_sel: 0 = g_state (+fp16 copy), 2 = dst_ext, 3 = g_xproj
__global__ void __launch_bounds__(256) gemm_kernel(
    const float* __restrict__ Aext, int a_sel,
    int use_bias, int dst_sel, float* __restrict__ dst_ext, int do_tanh)
{
    __shared__ unsigned sWhi[HID * PU];
    __shared__ unsigned sWlo[HID * PU];
    __shared__ unsigned sAhi[GR * PU];
    __shared__ unsigned sAlo[GR * PU];

    const float* A = (a_sel == 1) ? g_state : Aext;
    float* dst = (dst_sel == 0) ? g_state :
                 (dst_sel == 2) ? dst_ext : g_xproj;

    int t = threadIdx.x;
    int lane = t & 31, wid = t >> 5;
    int gid = lane >> 2, tig = lane & 3;
    int wm = wid & 1, wn = wid >> 1;          // 2 m-tiles x 4 n-tiles
    int m_w = wm * 32, n_w = wn * 32;
    int row0 = blockIdx.x * GR;

    // ldmatrix per-lane shared addresses (byte addressing)
    unsigned bAhi = (unsigned)__cvta_generic_to_shared(sAhi);
    unsigned bAlo = (unsigned)__cvta_generic_to_shared(sAlo);
    unsigned bWhi = (unsigned)__cvta_generic_to_shared(sWhi);
    unsigned bWlo = (unsigned)__cvta_generic_to_shared(sWlo);
    int l7 = lane & 7;
    int arow = m_w + l7 + (lane & 8);             // +8 for lanes 8-15, 24-31
    unsigned aoff = (lane & 16) ? 16u : 0u;       // k8-15 half for lanes 16-31
    unsigned adrA0hi = bAhi + (unsigned)((arow)      * PU) * 4u + aoff;
    unsigned adrA1hi = bAhi + (unsigned)((arow + 16) * PU) * 4u + aoff;
    unsigned adrA0lo = bAlo + (unsigned)((arow)      * PU) * 4u + aoff;
    unsigned adrA1lo = bAlo + (unsigned)((arow + 16) * PU) * 4u + aoff;
    int wrow = n_w + l7;
    unsigned woff = (lane & 8) ? 16u : 0u;        // k8-15 half for lanes 8-15
    unsigned adrWhi = bWhi + (unsigned)(wrow * PU) * 4u + woff;
    unsigned adrWlo = bWlo + (unsigned)(wrow * PU) * 4u + woff;

    // tile-load index precompute
    int wr0 = t >> 2,          wq0 = (t & 3) * 4;          // W idx t
    int wr1 = (t + 256) >> 2,  wq1 = ((t + 256) & 3) * 4;  // W idx t+256
    int ar  = t >> 2,          aq  = (t & 3) * 4;          // A presplit idx t
    int fr0 = t >> 3,          fc0 = (t & 7) * 4;          // A fp32 idx t
    int fr1 = (t + 256) >> 3,  fc1 = ((t + 256) & 7) * 4;  // A fp32 idx t+256

    uint4 pwh0, pwh1, pwl0, pwl1, pah, pal;
    float4 paf0, paf1;

    #define LOAD_CHUNK(K20) do {                                             \
        pwh0 = *(const uint4*)&g_whi[wr0 * WPK + (K20) + wq0];               \
        pwh1 = *(const uint4*)&g_whi[wr1 * WPK + (K20) + wq1];               \
        pwl0 = *(const uint4*)&g_wlo[wr0 * WPK + (K20) + wq0];               \
        pwl1 = *(const uint4*)&g_wlo[wr1 * WPK + (K20) + wq1];               \
        if (a_sel == 2) {                                                    \
            pah = *(const uint4*)&g_aggrhi[(row0 + ar) * WPK + (K20) + aq];  \
            pal = *(const uint4*)&g_aggrlo[(row0 + ar) * WPK + (K20) + aq];  \
        } else {                                                             \
            paf0 = *(const float4*)&A[(row0 + fr0) * HID + (K20) * 2 + fc0]; \
            paf1 = *(const float4*)&A[(row0 + fr1) * HID + (K20) * 2 + fc1]; \
        }                                                                    \
    } while (0)

    #define STORE_CHUNK() do {                                               \
        *(uint4*)&sWhi[wr0 * PU + wq0] = pwh0;                               \
        *(uint4*)&sWhi[wr1 * PU + wq1] = pwh1;                               \
        *(uint4*)&sWlo[wr0 * PU + wq0] = pwl0;                               \
        *(uint4*)&sWlo[wr1 * PU + wq1] = pwl1;                               \
        if (a_sel == 2) {                                                    \
            *(uint4*)&sAhi[ar * PU + aq] = pah;                              \
            *(uint4*)&sAlo[ar * PU + aq] = pal;                              \
        } else {                                                             \
            unsigned h0, l0, h1, l1;                                         \
            split_pair(paf0.x, paf0.y, h0, l0);                              \
            split_pair(paf0.z, paf0.w, h1, l1);                              \
            int s0 = fr0 * PU + fc0 / 2;                                     \
            sAhi[s0] = h0; sAhi[s0 + 1] = h1;                                \
            sAlo[s0] = l0; sAlo[s0 + 1] = l1;                                \
            split_pair(paf1.x, paf1.y, h0, l0);                              \
            split_pair(paf1.z, paf1.w, h1, l1);                              \
            int s1 = fr1 * PU + fc1 / 2;                                     \
            sAhi[s1] = h0; sAhi[s1 + 1] = h1;                                \
            sAlo[s1] = l0; sAlo[s1 + 1] = l1;                                \
        }                                                                    \
    } while (0)

    float acc[2][4][4];
#pragma unroll
    for (int mi = 0; mi < 2; mi++)
#pragma unroll
        for (int ni = 0; ni < 4; ni++)
#pragma unroll
            for (int q = 0; q < 4; q++) acc[mi][ni][q] = 0.f;

    LOAD_CHUNK(0);
    STORE_CHUNK();
    __syncthreads();

#pragma unroll
    for (int c = 0; c < 4; c++) {
        if (c < 3) LOAD_CHUNK((c + 1) * (KT / 2));   // issue next chunk's LDGs early

#pragma unroll
        for (int ks = 0; ks < 2; ks++) {
            unsigned ko = ks * 32u;     // 8 u32 = 32 bytes
            unsigned ah[2][4], al[2][4];
            ldsm_x4(ah[0], adrA0hi + ko);
            ldsm_x4(ah[1], adrA1hi + ko);
            ldsm_x4(al[0], adrA0lo + ko);
            ldsm_x4(al[1], adrA1lo + ko);
#pragma unroll
            for (int ni = 0; ni < 4; ni++) {
                unsigned wofs = ko + (unsigned)(ni * 8 * PU) * 4u;
                unsigned bh0, bh1, bl0, bl1;
                ldsm_x2(bh0, bh1, adrWhi + wofs);
                ldsm_x2(bl0, bl1, adrWlo + wofs);
#pragma unroll
                for (int mi = 0; mi < 2; mi++) {
                    mma_bf16(acc[mi][ni][0], acc[mi][ni][1],
                             acc[mi][ni][2], acc[mi][ni][3],
                             ah[mi][0], ah[mi][1], ah[mi][2], ah[mi][3],
                             bh0, bh1);
                    mma_bf16(acc[mi][ni][0], acc[mi][ni][1],
                             acc[mi][ni][2], acc[mi][ni][3],
                             ah[mi][0], ah[mi][1], ah[mi][2], ah[mi][3],
                             bl0, bl1);
                    mma_bf16(acc[mi][ni][0], acc[mi][ni][1],
                             acc[mi][ni][2], acc[mi][ni][3],
                             al[mi][0], al[mi][1], al[mi][2], al[mi][3],
                             bh0, bh1);
                }
            }
        }
        __syncthreads();             // all warps done reading smem
        if (c < 3) {
            STORE_CHUNK();           // overwrite with prefetched chunk
            __syncthreads();
        }
    }
    #undef LOAD_CHUNK
    #undef STORE_CHUNK

#pragma unroll
    for (int mi = 0; mi < 2; mi++) {
        int ra = row0 + m_w + mi * 16 + gid;
        int rb = ra + 8;
#pragma unroll
        for (int ni = 0; ni < 4; ni++) {
            int col = n_w + ni * 8 + tig * 2;
            float v0 = acc[mi][ni][0], v1 = acc[mi][ni][1];
            float v2 = acc[mi][ni][2], v3 = acc[mi][ni][3];
            if (use_bias) {
                float2 ba = *(const float2*)&g_xproj[ra * HID + col];
                float2 bb = *(const float2*)&g_xproj[rb * HID + col];
                v0 += ba.x; v1 += ba.y; v2 += bb.x; v3 += bb.y;
            }
            if (do_tanh) {
                v0 = tanhf(v0); v1 = tanhf(v1);
                v2 = tanhf(v2); v3 = tanhf(v3);
            }
            *(float2*)&dst[ra * HID + col] = make_float2(v0, v1);
            *(float2*)&dst[rb * HID + col] = make_float2(v2, v3);
            if (dst_sel == 0) {
                *(__half2*)&g_stateH[ra * HID + col] =
                    __floats2half2_rn(v0, v1);
                *(__half2*)&g_stateH[rb * HID + col] =
                    __floats2half2_rn(v2, v3);
            }
        }
    }
}

// ---------------- host orchestration ----------------
extern "C" void kernel_launch(void* const* d_in, const int* in_sizes, int n_in,
                              void* d_out, int out_size)
{
    const void* ei = nullptr;
    const float* x = nullptr;
    const float* w[4] = {nullptr, nullptr, nullptr, nullptr};
    int wn = 0;
    for (int i = 0; i < n_in; i++) {
        if (in_sizes[i] == 2 * N_EDGES)      ei = d_in[i];
        else if (in_sizes[i] == NH)          x  = (const float*)d_in[i];
        else if (in_sizes[i] == HID * HID && wn < 4) w[wn++] = (const float*)d_in[i];
    }
    const float* w_in0  = w[0];
    const float* w_rec0 = w[1];
    const float* w_in1  = w[2];
    const float* w_rec1 = w[3];
    float* out = (float*)d_out;

    const int BLOCKS = N_NODES / GR;             // 625
    const int TANH_BLOCKS = (NH + 255) / 256;
    const int AGGR_BLOCKS = (N_NODES + 7) / 8;   // 5000
    const int SPLITW_BLOCKS = (HID * WPK + 255) / 256;  // 32

    // order chosen so launch idx 3 = gemm_kernel (the one ncu profiles)
    detect_kernel<<<1, 32>>>(ei);                            // 0
    zero_counts_kernel<<<40, 1024>>>();                      // 1
    split_w_kernel<<<SPLITW_BLOCKS, 256>>>(w_in0, 0);        // 2
    gemm_kernel<<<BLOCKS, 256>>>(x, 0, 0, 3, nullptr, 0);    // 3: xproj = x @ win0^T
    hist_kernel<<<(N_EDGES + 255) / 256, 256>>>(ei);         // 4
    scan_a_kernel<<<NSCB, 256>>>();
    scan_b_kernel<<<1, 256>>>();
    scan_c_kernel<<<NSCB, 256>>>();
    fill_kernel<<<(N_EDGES + 255) / 256, 256>>>(ei);
    tanh_kernel<<<TANH_BLOCKS, 256>>>();                     // state = tanh(xproj)

    for (int layer = 0; layer < 2; layer++) {
        if (layer == 1) {
            split_w_kernel<<<SPLITW_BLOCKS, 256>>>(w_in1, 0);
            gemm_kernel<<<BLOCKS, 256>>>(nullptr, 1, 0, 3, nullptr, 0);
            tanh_kernel<<<TANH_BLOCKS, 256>>>();
        }
        const float* wrec = layer ? w_rec1 : w_rec0;
        split_w_kernel<<<SPLITW_BLOCKS, 256>>>(wrec, 1);

        for (int it = 0; it < 8; it++) {
            aggregate_kernel<<<AGGR_BLOCKS, 256>>>();
            int last = (layer == 1 && it == 7);
            gemm_kernel<<<BLOCKS, 256>>>(
                nullptr, /*A=presplit aggr*/ 2,
                /*bias*/ 1, last ? 2 : 0, last ? out : nullptr, /*tanh*/ 1);
        }
    }
}

// round 15
// speedup vs baseline: 1.0221x; 1.0221x over previous
#include <cuda_runtime.h>
#include <cuda_bf16.h>
#include <cuda_fp16.h>
#include <math.h>

#define N_NODES 40000
#define N_EDGES 640000
#define HID     128
#define NH      (N_NODES * HID)
#define NPAD    40960   // padded count array (160 blocks * 256)
#define NSCB    160     // scan blocks
#define WPK     64      // u32 per row in presplit arrays (128 k / 2)

// ---------------- device scratch (no allocations allowed) ----------------
__device__ __align__(16) float  g_xproj[NH];
__device__ __align__(16) float  g_state[NH];
__device__ __align__(16) __half g_stateH[NH];     // fp16 gather copy
__device__ __align__(16) unsigned g_aggrhi[N_NODES * WPK];
__device__ __align__(16) unsigned g_aggrlo[N_NODES * WPK];
__device__ __align__(16) unsigned g_whi[HID * WPK];
__device__ __align__(16) unsigned g_wlo[HID * WPK];
__device__ int   g_rowptr[N_NODES + 1];
__device__ int   g_cursor[N_NODES];
__device__ __align__(16) int g_counts[NPAD];
__device__ int   g_col[N_EDGES];
__device__ int   g_bsum[NSCB];
__device__ int   g_boff[NSCB];
__device__ int   g_is64;

// ---------------- bf16 split + mma helpers ----------------
__device__ __forceinline__ void split_pair(float x, float y,
                                           unsigned& hi, unsigned& lo) {
    __nv_bfloat16 hx = __float2bfloat16_rn(x);
    __nv_bfloat16 hy = __float2bfloat16_rn(y);
    __nv_bfloat16 lx = __float2bfloat16_rn(x - __bfloat162float(hx));
    __nv_bfloat16 ly = __float2bfloat16_rn(y - __bfloat162float(hy));
    hi = (unsigned)__bfloat16_as_ushort(hx) |
         ((unsigned)__bfloat16_as_ushort(hy) << 16);
    lo = (unsigned)__bfloat16_as_ushort(lx) |
         ((unsigned)__bfloat16_as_ushort(ly) << 16);
}

__device__ __forceinline__ void mma_bf16(
    float& c0, float& c1, float& c2, float& c3,
    unsigned a0, unsigned a1, unsigned a2, unsigned a3,
    unsigned b0, unsigned b1)
{
    asm("mma.sync.aligned.m16n8k16.row.col.f32.bf16.bf16.f32 "
        "{%0,%1,%2,%3}, {%4,%5,%6,%7}, {%8,%9}, {%0,%1,%2,%3};"
        : "+f"(c0), "+f"(c1), "+f"(c2), "+f"(c3)
        : "r"(a0), "r"(a1), "r"(a2), "r"(a3), "r"(b0), "r"(b1));
}

// ---------------- edge dtype probe: int64 vs int32 ----------------
__global__ void detect_kernel(const void* ei) {
    if (threadIdx.x == 0 && blockIdx.x == 0) {
        const long long* p = (const long long*)ei;
        int ok64 = 1;
        for (int i = 0; i < 64; i++) {
            long long v = p[(i * 9973) % 640000];
            if (v < 0 || v >= N_NODES) { ok64 = 0; break; }
        }
        g_is64 = ok64;
    }
}

__device__ __forceinline__ int edge_val(const void* ei, int idx) {
    int v;
    if (g_is64) v = (int)((const long long*)ei)[idx];
    else        v = ((const int*)ei)[idx];
    return ((unsigned)v < N_NODES) ? v : 0;   // clamp: never trap
}

// ---------------- weight pre-split ----------------
__global__ void split_w_kernel(const float* __restrict__ w, int transpose) {
    int idx = blockIdx.x * blockDim.x + threadIdx.x;   // 0..8191
    if (idx >= HID * WPK) return;
    int n = idx >> 6, k2 = idx & 63;
    int k = k2 * 2;
    float a = transpose ? w[k * HID + n]       : w[n * HID + k];
    float b = transpose ? w[(k + 1) * HID + n] : w[n * HID + k + 1];
    unsigned hi, lo;
    split_pair(a, b, hi, lo);
    g_whi[idx] = hi;
    g_wlo[idx] = lo;
}

// ---------------- CSR build ----------------
__global__ void zero_counts_kernel() {
    for (int i = blockIdx.x * blockDim.x + threadIdx.x; i < NPAD;
         i += gridDim.x * blockDim.x)
        g_counts[i] = 0;
}

__global__ void hist_kernel(const void* __restrict__ ei) {
    int e = blockIdx.x * blockDim.x + threadIdx.x;
    if (e < N_EDGES) {
        int dst = edge_val(ei, N_EDGES + e);
        atomicAdd(&g_counts[dst], 1);
    }
}

__global__ void scan_a_kernel() {
    __shared__ int ws[8];
    int t = threadIdx.x, lane = t & 31, wid = t >> 5;
    int v = g_counts[blockIdx.x * 256 + t];
    int s = v;
    for (int o = 16; o > 0; o >>= 1) s += __shfl_down_sync(0xffffffffu, s, o);
    if (lane == 0) ws[wid] = s;
    __syncthreads();
    if (t == 0) {
        int tot = 0;
        for (int i = 0; i < 8; i++) tot += ws[i];
        g_bsum[blockIdx.x] = tot;
    }
}

__global__ void scan_b_kernel() {
    __shared__ int woff[8];
    int t = threadIdx.x, lane = t & 31, wid = t >> 5;
    int v = (t < NSCB) ? g_bsum[t] : 0;
    int p = v;
    for (int o = 1; o < 32; o <<= 1) {
        int n = __shfl_up_sync(0xffffffffu, p, o);
        if (lane >= o) p += n;
    }
    if (lane == 31) woff[wid] = p;
    __syncthreads();
    if (wid == 0) {
        int w = (lane < 8) ? woff[lane] : 0;
        int q = w;
        for (int o = 1; o < 8; o <<= 1) {
            int n = __shfl_up_sync(0xffffffffu, q, o);
            if (lane >= o) q += n;
        }
        if (lane < 8) woff[lane] = q - w;
    }
    __syncthreads();
    if (t < NSCB) g_boff[t] = woff[wid] + (p - v);
}

__global__ void scan_c_kernel() {
    __shared__ int woff[8];
    int t = threadIdx.x, lane = t & 31, wid = t >> 5;
    int i = blockIdx.x * 256 + t;
    int v = g_counts[i];
    int p = v;
    for (int o = 1; o < 32; o <<= 1) {
        int n = __shfl_up_sync(0xffffffffu, p, o);
        if (lane >= o) p += n;
    }
    if (lane == 31) woff[wid] = p;
    __syncthreads();
    if (wid == 0) {
        int w = (lane < 8) ? woff[lane] : 0;
        int q = w;
        for (int o = 1; o < 8; o <<= 1) {
            int n = __shfl_up_sync(0xffffffffu, q, o);
            if (lane >= o) q += n;
        }
        if (lane < 8) woff[lane] = q - w;
    }
    __syncthreads();
    int excl = g_boff[blockIdx.x] + woff[wid] + (p - v);
    if (i < N_NODES) {
        g_cursor[i] = excl;
        g_rowptr[i + 1] = excl + v;
    }
    if (i == 0) g_rowptr[0] = 0;
}

__global__ void fill_kernel(const void* __restrict__ ei) {
    int e = blockIdx.x * blockDim.x + threadIdx.x;
    if (e < N_EDGES) {
        int src = edge_val(ei, e);
        int dst = edge_val(ei, N_EDGES + e);
        int pos = atomicAdd(&g_cursor[dst], 1);
        if ((unsigned)pos < N_EDGES) g_col[pos] = src;
    }
}

// ---------------- edge aggregation: warp/node, fp16 gather (unroll 2) --------
__global__ void __launch_bounds__(256) aggregate_kernel() {
    int node = blockIdx.x * 8 + (threadIdx.x >> 5);
    if (node >= N_NODES) return;
    int lane = threadIdx.x & 31;
    int s = g_rowptr[node];
    int e = g_rowptr[node + 1];
    const uint2* st = (const uint2*)g_stateH;    // 32 uint2 (=4 halves) per node
    float4 acc = make_float4(0.f, 0.f, 0.f, 0.f);
    int i = s;
    for (; i + 1 < e; i += 2) {
        uint2 ua = st[g_col[i]     * 32 + lane];
        uint2 ub = st[g_col[i + 1] * 32 + lane];
        float2 a01 = __half22float2(*(__half2*)&ua.x);
        float2 a23 = __half22float2(*(__half2*)&ua.y);
        float2 b01 = __half22float2(*(__half2*)&ub.x);
        float2 b23 = __half22float2(*(__half2*)&ub.y);
        acc.x += a01.x + b01.x; acc.y += a01.y + b01.y;
        acc.z += a23.x + b23.x; acc.w += a23.y + b23.y;
    }
    if (i < e) {
        uint2 u = st[g_col[i] * 32 + lane];
        float2 f01 = __half22float2(*(__half2*)&u.x);
        float2 f23 = __half22float2(*(__half2*)&u.y);
        acc.x += f01.x; acc.y += f01.y; acc.z += f23.x; acc.w += f23.y;
    }
    unsigned h0, l0, h1, l1;
    split_pair(acc.x, acc.y, h0, l0);
    split_pair(acc.z, acc.w, h1, l1);
    int base = node * WPK + lane * 2;
    *(uint2*)&g_aggrhi[base] = make_uint2(h0, h1);
    *(uint2*)&g_aggrlo[base] = make_uint2(l0, l1);
}

// ---------------- bf16-split tensor-core GEMM (register-prefetch pipeline) ----
// dst[m][n] = f((bias? xproj) + sum_k A[m][k] * W[n][k])
// A@W ~= Ahi@Whi + Ahi@Wlo + Alo@Whi  (fp32 accum, mma.m16n8k16.bf16)
// 256 threads (8 warps), block tile 64(m) x 128(n), warp tile m32 x n32.
#define GR 64
#define KT 32
#define PU 20    // u32 per smem row (16 data + 4 pad), conflict-free

// a_sel: 0 = Aext(fp32), 1 = g_state(fp32), 2 = presplit g_aggrhi/lo
// dst_sel: 0 = g_state (+fp16 copy), 2 = dst_ext, 3 = g_xproj,
//          4 = proj+tanh fused: xproj = pre, state/stateH = tanh(pre)
__global__ void __launch_bounds__(256) gemm_kernel(
    const float* __restrict__ Aext, int a_sel,
    int use_bias, int dst_sel, float* __restrict__ dst_ext, int do_tanh)
{
    __shared__ unsigned sWhi[HID * PU];
    __shared__ unsigned sWlo[HID * PU];
    __shared__ unsigned sAhi[GR * PU];
    __shared__ unsigned sAlo[GR * PU];

    const float* A = (a_sel == 1) ? g_state : Aext;
    float* dst = (dst_sel == 0) ? g_state :
                 (dst_sel == 2) ? dst_ext : g_xproj;

    int t = threadIdx.x;
    int lane = t & 31, wid = t >> 5;
    int gid = lane >> 2, tig = lane & 3;
    int wm = wid & 1, wn = wid >> 1;          // 2 m-tiles x 4 n-tiles
    int m_w = wm * 32, n_w = wn * 32;
    int row0 = blockIdx.x * GR;

    // tile-load index precompute
    int wr0 = t >> 2,          wq0 = (t & 3) * 4;          // W idx t
    int wr1 = (t + 256) >> 2,  wq1 = ((t + 256) & 3) * 4;  // W idx t+256
    int ar  = t >> 2,          aq  = (t & 3) * 4;          // A presplit idx t
    int fr0 = t >> 3,          fc0 = (t & 7) * 4;          // A fp32 idx t
    int fr1 = (t + 256) >> 3,  fc1 = ((t + 256) & 7) * 4;  // A fp32 idx t+256

    uint4 pwh0, pwh1, pwl0, pwl1, pah, pal;
    float4 paf0, paf1;

    #define LOAD_CHUNK(K20) do {                                             \
        pwh0 = *(const uint4*)&g_whi[wr0 * WPK + (K20) + wq0];               \
        pwh1 = *(const uint4*)&g_whi[wr1 * WPK + (K20) + wq1];               \
        pwl0 = *(const uint4*)&g_wlo[wr0 * WPK + (K20) + wq0];               \
        pwl1 = *(const uint4*)&g_wlo[wr1 * WPK + (K20) + wq1];               \
        if (a_sel == 2) {                                                    \
            pah = *(const uint4*)&g_aggrhi[(row0 + ar) * WPK + (K20) + aq];  \
            pal = *(const uint4*)&g_aggrlo[(row0 + ar) * WPK + (K20) + aq];  \
        } else {                                                             \
            paf0 = *(const float4*)&A[(row0 + fr0) * HID + (K20) * 2 + fc0]; \
            paf1 = *(const float4*)&A[(row0 + fr1) * HID + (K20) * 2 + fc1]; \
        }                                                                    \
    } while (0)

    #define STORE_CHUNK() do {                                               \
        *(uint4*)&sWhi[wr0 * PU + wq0] = pwh0;                               \
        *(uint4*)&sWhi[wr1 * PU + wq1] = pwh1;                               \
        *(uint4*)&sWlo[wr0 * PU + wq0] = pwl0;                               \
        *(uint4*)&sWlo[wr1 * PU + wq1] = pwl1;                               \
        if (a_sel == 2) {                                                    \
            *(uint4*)&sAhi[ar * PU + aq] = pah;                              \
            *(uint4*)&sAlo[ar * PU + aq] = pal;                              \
        } else {                                                             \
            unsigned h0, l0, h1, l1;                                         \
            split_pair(paf0.x, paf0.y, h0, l0);                              \
            split_pair(paf0.z, paf0.w, h1, l1);                              \
            int s0 = fr0 * PU + fc0 / 2;                                     \
            sAhi[s0] = h0; sAhi[s0 + 1] = h1;                                \
            sAlo[s0] = l0; sAlo[s0 + 1] = l1;                                \
            split_pair(paf1.x, paf1.y, h0, l0);                              \
            split_pair(paf1.z, paf1.w, h1, l1);                              \
            int s1 = fr1 * PU + fc1 / 2;                                     \
            sAhi[s1] = h0; sAhi[s1 + 1] = h1;                                \
            sAlo[s1] = l0; sAlo[s1 + 1] = l1;                                \
        }                                                                    \
    } while (0)

    float acc[2][4][4];
#pragma unroll
    for (int mi = 0; mi < 2; mi++)
#pragma unroll
        for (int ni = 0; ni < 4; ni++)
#pragma unroll
            for (int q = 0; q < 4; q++) acc[mi][ni][q] = 0.f;

    LOAD_CHUNK(0);
    STORE_CHUNK();
    __syncthreads();

#pragma unroll
    for (int c = 0; c < 4; c++) {
        if (c < 3) LOAD_CHUNK((c + 1) * (KT / 2));   // issue next chunk's LDGs early

#pragma unroll
        for (int ks = 0; ks < 2; ks++) {
            int ko = ks * 8;
            unsigned ah[2][4], al[2][4];
#pragma unroll
            for (int mi = 0; mi < 2; mi++) {
                int ab = (m_w + mi * 16 + gid) * PU + ko + tig;
                ah[mi][0] = sAhi[ab];
                ah[mi][1] = sAhi[ab + 8 * PU];
                ah[mi][2] = sAhi[ab + 4];
                ah[mi][3] = sAhi[ab + 8 * PU + 4];
                al[mi][0] = sAlo[ab];
                al[mi][1] = sAlo[ab + 8 * PU];
                al[mi][2] = sAlo[ab + 4];
                al[mi][3] = sAlo[ab + 8 * PU + 4];
            }
#pragma unroll
            for (int ni = 0; ni < 4; ni++) {
                int bb = (n_w + ni * 8 + gid) * PU + ko + tig;
                unsigned bh0 = sWhi[bb], bh1 = sWhi[bb + 4];
                unsigned bl0 = sWlo[bb], bl1 = sWlo[bb + 4];
#pragma unroll
                for (int mi = 0; mi < 2; mi++) {
                    mma_bf16(acc[mi][ni][0], acc[mi][ni][1],
                             acc[mi][ni][2], acc[mi][ni][3],
                             ah[mi][0], ah[mi][1], ah[mi][2], ah[mi][3],
                             bh0, bh1);
                    mma_bf16(acc[mi][ni][0], acc[mi][ni][1],
                             acc[mi][ni][2], acc[mi][ni][3],
                             ah[mi][0], ah[mi][1], ah[mi][2], ah[mi][3],
                             bl0, bl1);
                    mma_bf16(acc[mi][ni][0], acc[mi][ni][1],
                             acc[mi][ni][2], acc[mi][ni][3],
                             al[mi][0], al[mi][1], al[mi][2], al[mi][3],
                             bh0, bh1);
                }
            }
        }
        __syncthreads();             // all warps done reading smem
        if (c < 3) {
            STORE_CHUNK();           // overwrite with prefetched chunk
            __syncthreads();
        }
    }
    #undef LOAD_CHUNK
    #undef STORE_CHUNK

#pragma unroll
    for (int mi = 0; mi < 2; mi++) {
        int ra = row0 + m_w + mi * 16 + gid;
        int rb = ra + 8;
#pragma unroll
        for (int ni = 0; ni < 4; ni++) {
            int col = n_w + ni * 8 + tig * 2;
            float v0 = acc[mi][ni][0], v1 = acc[mi][ni][1];
            float v2 = acc[mi][ni][2], v3 = acc[mi][ni][3];
            if (use_bias) {
                float2 ba = *(const float2*)&g_xproj[ra * HID + col];
                float2 bb = *(const float2*)&g_xproj[rb * HID + col];
                v0 += ba.x; v1 += ba.y; v2 += bb.x; v3 += bb.y;
            }
            if (dst_sel == 4) {
                // fused projection: xproj = pre, state = tanh(pre), stateH copy
                *(float2*)&g_xproj[ra * HID + col] = make_float2(v0, v1);
                *(float2*)&g_xproj[rb * HID + col] = make_float2(v2, v3);
                v0 = tanhf(v0); v1 = tanhf(v1);
                v2 = tanhf(v2); v3 = tanhf(v3);
                *(float2*)&g_state[ra * HID + col] = make_float2(v0, v1);
                *(float2*)&g_state[rb * HID + col] = make_float2(v2, v3);
                *(__half2*)&g_stateH[ra * HID + col] = __floats2half2_rn(v0, v1);
                *(__half2*)&g_stateH[rb * HID + col] = __floats2half2_rn(v2, v3);
                continue;
            }
            if (do_tanh) {
                v0 = tanhf(v0); v1 = tanhf(v1);
                v2 = tanhf(v2); v3 = tanhf(v3);
            }
            *(float2*)&dst[ra * HID + col] = make_float2(v0, v1);
            *(float2*)&dst[rb * HID + col] = make_float2(v2, v3);
            if (dst_sel == 0) {
                *(__half2*)&g_stateH[ra * HID + col] =
                    __floats2half2_rn(v0, v1);
                *(__half2*)&g_stateH[rb * HID + col] =
                    __floats2half2_rn(v2, v3);
            }
        }
    }
}

// ---------------- host orchestration ----------------
extern "C" void kernel_launch(void* const* d_in, const int* in_sizes, int n_in,
                              void* d_out, int out_size)
{
    const void* ei = nullptr;
    const float* x = nullptr;
    const float* w[4] = {nullptr, nullptr, nullptr, nullptr};
    int wn = 0;
    for (int i = 0; i < n_in; i++) {
        if (in_sizes[i] == 2 * N_EDGES)      ei = d_in[i];
        else if (in_sizes[i] == NH)          x  = (const float*)d_in[i];
        else if (in_sizes[i] == HID * HID && wn < 4) w[wn++] = (const float*)d_in[i];
    }
    const float* w_in0  = w[0];
    const float* w_rec0 = w[1];
    const float* w_in1  = w[2];
    const float* w_rec1 = w[3];
    float* out = (float*)d_out;

    const int BLOCKS = N_NODES / GR;             // 625
    const int AGGR_BLOCKS = (N_NODES + 7) / 8;   // 5000
    const int SPLITW_BLOCKS = (HID * WPK + 255) / 256;  // 32

    // order chosen so launch idx 3 = gemm_kernel (the one ncu profiles)
    detect_kernel<<<1, 32>>>(ei);                            // 0
    zero_counts_kernel<<<40, 1024>>>();                      // 1
    split_w_kernel<<<SPLITW_BLOCKS, 256>>>(w_in0, 0);        // 2
    gemm_kernel<<<BLOCKS, 256>>>(x, 0, 0, 4, nullptr, 0);    // 3: fused proj+tanh
    hist_kernel<<<(N_EDGES + 255) / 256, 256>>>(ei);         // 4
    scan_a_kernel<<<NSCB, 256>>>();
    scan_b_kernel<<<1, 256>>>();
    scan_c_kernel<<<NSCB, 256>>>();
    fill_kernel<<<(N_EDGES + 255) / 256, 256>>>(ei);

    for (int layer = 0; layer < 2; layer++) {
        if (layer == 1) {
            // layer-1 fused projection: xproj = state @ win1^T; state = tanh
            split_w_kernel<<<SPLITW_BLOCKS, 256>>>(w_in1, 0);
            gemm_kernel<<<BLOCKS, 256>>>(nullptr, 1, 0, 4, nullptr, 0);
        }
        const float* wrec = layer ? w_rec1 : w_rec0;
        split_w_kernel<<<SPLITW_BLOCKS, 256>>>(wrec, 1);

        for (int it = 0; it < 8; it++) {
            aggregate_kernel<<<AGGR_BLOCKS, 256>>>();
            int last = (layer == 1 && it == 7);
            gemm_kernel<<<BLOCKS, 256>>>(
                nullptr, /*A=presplit aggr*/ 2,
                /*bias*/ 1, last ? 2 : 0, last ? out : nullptr, /*tanh*/ 1);
        }
    }
}

// round 16
// speedup vs baseline: 1.1657x; 1.1405x over previous
#include <cuda_runtime.h>
#include <cuda_bf16.h>
#include <cuda_fp16.h>
#include <math.h>

#define N_NODES 40000
#define N_EDGES 640000
#define HID     128
#define NH      (N_NODES * HID)
#define NPAD    40960   // padded count array (160 blocks * 256)
#define NSCB    160     // scan blocks
#define WPK     64      // u32 per row in presplit / fp16 arrays (128 vals / 2)

// ---------------- device scratch (no allocations allowed) ----------------
__device__ __align__(16) float  g_xproj[NH];
__device__ __align__(16) float  g_state[NH];
__device__ __align__(16) __half g_stateH[NH];          // fp16 gather copy
__device__ __align__(16) unsigned g_aggrH[N_NODES * WPK];  // fp16 aggr (packed)
__device__ __align__(16) unsigned g_whi[HID * WPK];    // W hi (bf16 or fp16)
__device__ __align__(16) unsigned g_wlo[HID * WPK];    // W lo
__device__ int   g_rowptr[N_NODES + 1];
__device__ int   g_cursor[N_NODES];
__device__ __align__(16) int g_counts[NPAD];
__device__ int   g_col[N_EDGES];
__device__ int   g_bsum[NSCB];
__device__ int   g_boff[NSCB];
__device__ int   g_is64;

// ---------------- split + mma helpers ----------------
__device__ __forceinline__ void split_pair_bf16(float x, float y,
                                                unsigned& hi, unsigned& lo) {
    __nv_bfloat16 hx = __float2bfloat16_rn(x);
    __nv_bfloat16 hy = __float2bfloat16_rn(y);
    __nv_bfloat16 lx = __float2bfloat16_rn(x - __bfloat162float(hx));
    __nv_bfloat16 ly = __float2bfloat16_rn(y - __bfloat162float(hy));
    hi = (unsigned)__bfloat16_as_ushort(hx) |
         ((unsigned)__bfloat16_as_ushort(hy) << 16);
    lo = (unsigned)__bfloat16_as_ushort(lx) |
         ((unsigned)__bfloat16_as_ushort(ly) << 16);
}

__device__ __forceinline__ void split_pair_f16(float x, float y,
                                               unsigned& hi, unsigned& lo) {
    __half hx = __float2half_rn(x);
    __half hy = __float2half_rn(y);
    __half lx = __float2half_rn(x - __half2float(hx));
    __half ly = __float2half_rn(y - __half2float(hy));
    hi = (unsigned)__half_as_ushort(hx) |
         ((unsigned)__half_as_ushort(hy) << 16);
    lo = (unsigned)__half_as_ushort(lx) |
         ((unsigned)__half_as_ushort(ly) << 16);
}

__device__ __forceinline__ void mma_bf16(
    float& c0, float& c1, float& c2, float& c3,
    unsigned a0, unsigned a1, unsigned a2, unsigned a3,
    unsigned b0, unsigned b1)
{
    asm("mma.sync.aligned.m16n8k16.row.col.f32.bf16.bf16.f32 "
        "{%0,%1,%2,%3}, {%4,%5,%6,%7}, {%8,%9}, {%0,%1,%2,%3};"
        : "+f"(c0), "+f"(c1), "+f"(c2), "+f"(c3)
        : "r"(a0), "r"(a1), "r"(a2), "r"(a3), "r"(b0), "r"(b1));
}

__device__ __forceinline__ void mma_f16(
    float& c0, float& c1, float& c2, float& c3,
    unsigned a0, unsigned a1, unsigned a2, unsigned a3,
    unsigned b0, unsigned b1)
{
    asm("mma.sync.aligned.m16n8k16.row.col.f32.f16.f16.f32 "
        "{%0,%1,%2,%3}, {%4,%5,%6,%7}, {%8,%9}, {%0,%1,%2,%3};"
        : "+f"(c0), "+f"(c1), "+f"(c2), "+f"(c3)
        : "r"(a0), "r"(a1), "r"(a2), "r"(a3), "r"(b0), "r"(b1));
}

// ---------------- edge dtype probe: int64 vs int32 ----------------
__global__ void detect_kernel(const void* ei) {
    if (threadIdx.x == 0 && blockIdx.x == 0) {
        const long long* p = (const long long*)ei;
        int ok64 = 1;
        for (int i = 0; i < 64; i++) {
            long long v = p[(i * 9973) % 640000];
            if (v < 0 || v >= N_NODES) { ok64 = 0; break; }
        }
        g_is64 = ok64;
    }
}

__device__ __forceinline__ int edge_val(const void* ei, int idx) {
    int v;
    if (g_is64) v = (int)((const long long*)ei)[idx];
    else        v = ((const int*)ei)[idx];
    return ((unsigned)v < N_NODES) ? v : 0;   // clamp: never trap
}

// ---------------- weight pre-split (bf16 for projection) ----------------
__global__ void split_w_bf16_kernel(const float* __restrict__ w) {
    int idx = blockIdx.x * blockDim.x + threadIdx.x;   // 0..8191
    if (idx >= HID * WPK) return;
    int n = idx >> 6, k2 = idx & 63;
    int k = k2 * 2;
    unsigned hi, lo;
    split_pair_bf16(w[n * HID + k], w[n * HID + k + 1], hi, lo);
    g_whi[idx] = hi;
    g_wlo[idx] = lo;
}

// ---------------- weight pre-split (fp16, transposed, for recurrent) ---------
__global__ void split_w_f16t_kernel(const float* __restrict__ w) {
    int idx = blockIdx.x * blockDim.x + threadIdx.x;   // 0..8191
    if (idx >= HID * WPK) return;
    int n = idx >> 6, k2 = idx & 63;
    int k = k2 * 2;
    unsigned hi, lo;
    split_pair_f16(w[k * HID + n], w[(k + 1) * HID + n], hi, lo);
    g_whi[idx] = hi;
    g_wlo[idx] = lo;
}

// ---------------- CSR build ----------------
__global__ void zero_counts_kernel() {
    for (int i = blockIdx.x * blockDim.x + threadIdx.x; i < NPAD;
         i += gridDim.x * blockDim.x)
        g_counts[i] = 0;
}

__global__ void hist_kernel(const void* __restrict__ ei) {
    int e = blockIdx.x * blockDim.x + threadIdx.x;
    if (e < N_EDGES) {
        int dst = edge_val(ei, N_EDGES + e);
        atomicAdd(&g_counts[dst], 1);
    }
}

__global__ void scan_a_kernel() {
    __shared__ int ws[8];
    int t = threadIdx.x, lane = t & 31, wid = t >> 5;
    int v = g_counts[blockIdx.x * 256 + t];
    int s = v;
    for (int o = 16; o > 0; o >>= 1) s += __shfl_down_sync(0xffffffffu, s, o);
    if (lane == 0) ws[wid] = s;
    __syncthreads();
    if (t == 0) {
        int tot = 0;
        for (int i = 0; i < 8; i++) tot += ws[i];
        g_bsum[blockIdx.x] = tot;
    }
}

__global__ void scan_b_kernel() {
    __shared__ int woff[8];
    int t = threadIdx.x, lane = t & 31, wid = t >> 5;
    int v = (t < NSCB) ? g_bsum[t] : 0;
    int p = v;
    for (int o = 1; o < 32; o <<= 1) {
        int n = __shfl_up_sync(0xffffffffu, p, o);
        if (lane >= o) p += n;
    }
    if (lane == 31) woff[wid] = p;
    __syncthreads();
    if (wid == 0) {
        int w = (lane < 8) ? woff[lane] : 0;
        int q = w;
        for (int o = 1; o < 8; o <<= 1) {
            int n = __shfl_up_sync(0xffffffffu, q, o);
            if (lane >= o) q += n;
        }
        if (lane < 8) woff[lane] = q - w;
    }
    __syncthreads();
    if (t < NSCB) g_boff[t] = woff[wid] + (p - v);
}

__global__ void scan_c_kernel() {
    __shared__ int woff[8];
    int t = threadIdx.x, lane = t & 31, wid = t >> 5;
    int i = blockIdx.x * 256 + t;
    int v = g_counts[i];
    int p = v;
    for (int o = 1; o < 32; o <<= 1) {
        int n = __shfl_up_sync(0xffffffffu, p, o);
        if (lane >= o) p += n;
    }
    if (lane == 31) woff[wid] = p;
    __syncthreads();
    if (wid == 0) {
        int w = (lane < 8) ? woff[lane] : 0;
        int q = w;
        for (int o = 1; o < 8; o <<= 1) {
            int n = __shfl_up_sync(0xffffffffu, q, o);
            if (lane >= o) q += n;
        }
        if (lane < 8) woff[lane] = q - w;
    }
    __syncthreads();
    int excl = g_boff[blockIdx.x] + woff[wid] + (p - v);
    if (i < N_NODES) {
        g_cursor[i] = excl;
        g_rowptr[i + 1] = excl + v;
    }
    if (i == 0) g_rowptr[0] = 0;
}

__global__ void fill_kernel(const void* __restrict__ ei) {
    int e = blockIdx.x * blockDim.x + threadIdx.x;
    if (e < N_EDGES) {
        int src = edge_val(ei, e);
        int dst = edge_val(ei, N_EDGES + e);
        int pos = atomicAdd(&g_cursor[dst], 1);
        if ((unsigned)pos < N_EDGES) g_col[pos] = src;
    }
}

// ---------------- edge aggregation: warp/node, fp16 in, fp16 out -------------
__global__ void __launch_bounds__(256) aggregate_kernel() {
    int node = blockIdx.x * 8 + (threadIdx.x >> 5);
    if (node >= N_NODES) return;
    int lane = threadIdx.x & 31;
    int s = g_rowptr[node];
    int e = g_rowptr[node + 1];
    const uint2* st = (const uint2*)g_stateH;    // 32 uint2 (=4 halves) per node
    float4 acc = make_float4(0.f, 0.f, 0.f, 0.f);
    for (int i = s; i < e; i++) {
        uint2 u = st[g_col[i] * 32 + lane];
        float2 f01 = __half22float2(*(__half2*)&u.x);
        float2 f23 = __half22float2(*(__half2*)&u.y);
        acc.x += f01.x; acc.y += f01.y; acc.z += f23.x; acc.w += f23.y;
    }
    __half2 h01 = __floats2half2_rn(acc.x, acc.y);
    __half2 h23 = __floats2half2_rn(acc.z, acc.w);
    uint2 outv;
    outv.x = *(unsigned*)&h01;
    outv.y = *(unsigned*)&h23;
    *(uint2*)&g_aggrH[node * WPK + lane * 2] = outv;
}

// ---------------- first state update: state = tanh(xproj), + fp16 copy --------
__global__ void tanh_kernel() {
    int i = blockIdx.x * blockDim.x + threadIdx.x;
    if (i < NH) {
        float v = tanhf(g_xproj[i]);
        g_state[i]  = v;
        g_stateH[i] = __float2half(v);
    }
}

// ======================= projection GEMM (bf16 3-pass) ========================
// xproj = A @ W^T, A fp32 (x or g_state), W presplit bf16 in g_whi/g_wlo.
#define GR 64
#define KT 32
#define PU 20

// a_sel: 0 = Aext(fp32), 1 = g_state(fp32)
__global__ void __launch_bounds__(256) gemm_proj_kernel(
    const float* __restrict__ Aext, int a_sel)
{
    __shared__ unsigned sWhi[HID * PU];
    __shared__ unsigned sWlo[HID * PU];
    __shared__ unsigned sAhi[GR * PU];
    __shared__ unsigned sAlo[GR * PU];

    const float* A = (a_sel == 1) ? g_state : Aext;

    int t = threadIdx.x;
    int lane = t & 31, wid = t >> 5;
    int gid = lane >> 2, tig = lane & 3;
    int wm = wid & 1, wn = wid >> 1;
    int m_w = wm * 32, n_w = wn * 32;
    int row0 = blockIdx.x * GR;

    int wr0 = t >> 2,          wq0 = (t & 3) * 4;
    int wr1 = (t + 256) >> 2,  wq1 = ((t + 256) & 3) * 4;
    int fr0 = t >> 3,          fc0 = (t & 7) * 4;
    int fr1 = (t + 256) >> 3,  fc1 = ((t + 256) & 7) * 4;

    uint4 pwh0, pwh1, pwl0, pwl1;
    float4 paf0, paf1;

    #define LOAD_CHUNK(K20) do {                                             \
        pwh0 = *(const uint4*)&g_whi[wr0 * WPK + (K20) + wq0];               \
        pwh1 = *(const uint4*)&g_whi[wr1 * WPK + (K20) + wq1];               \
        pwl0 = *(const uint4*)&g_wlo[wr0 * WPK + (K20) + wq0];               \
        pwl1 = *(const uint4*)&g_wlo[wr1 * WPK + (K20) + wq1];               \
        paf0 = *(const float4*)&A[(row0 + fr0) * HID + (K20) * 2 + fc0];     \
        paf1 = *(const float4*)&A[(row0 + fr1) * HID + (K20) * 2 + fc1];     \
    } while (0)

    #define STORE_CHUNK() do {                                               \
        *(uint4*)&sWhi[wr0 * PU + wq0] = pwh0;                               \
        *(uint4*)&sWhi[wr1 * PU + wq1] = pwh1;                               \
        *(uint4*)&sWlo[wr0 * PU + wq0] = pwl0;                               \
        *(uint4*)&sWlo[wr1 * PU + wq1] = pwl1;                               \
        unsigned h0, l0, h1, l1;                                             \
        split_pair_bf16(paf0.x, paf0.y, h0, l0);                             \
        split_pair_bf16(paf0.z, paf0.w, h1, l1);                             \
        int s0 = fr0 * PU + fc0 / 2;                                         \
        sAhi[s0] = h0; sAhi[s0 + 1] = h1;                                    \
        sAlo[s0] = l0; sAlo[s0 + 1] = l1;                                    \
        split_pair_bf16(paf1.x, paf1.y, h0, l0);                             \
        split_pair_bf16(paf1.z, paf1.w, h1, l1);                             \
        int s1 = fr1 * PU + fc1 / 2;                                         \
        sAhi[s1] = h0; sAhi[s1 + 1] = h1;                                    \
        sAlo[s1] = l0; sAlo[s1 + 1] = l1;                                    \
    } while (0)

    float acc[2][4][4];
#pragma unroll
    for (int mi = 0; mi < 2; mi++)
#pragma unroll
        for (int ni = 0; ni < 4; ni++)
#pragma unroll
            for (int q = 0; q < 4; q++) acc[mi][ni][q] = 0.f;

    LOAD_CHUNK(0);
    STORE_CHUNK();
    __syncthreads();

#pragma unroll
    for (int c = 0; c < 4; c++) {
        if (c < 3) LOAD_CHUNK((c + 1) * (KT / 2));

#pragma unroll
        for (int ks = 0; ks < 2; ks++) {
            int ko = ks * 8;
            unsigned ah[2][4], al[2][4];
#pragma unroll
            for (int mi = 0; mi < 2; mi++) {
                int ab = (m_w + mi * 16 + gid) * PU + ko + tig;
                ah[mi][0] = sAhi[ab];
                ah[mi][1] = sAhi[ab + 8 * PU];
                ah[mi][2] = sAhi[ab + 4];
                ah[mi][3] = sAhi[ab + 8 * PU + 4];
                al[mi][0] = sAlo[ab];
                al[mi][1] = sAlo[ab + 8 * PU];
                al[mi][2] = sAlo[ab + 4];
                al[mi][3] = sAlo[ab + 8 * PU + 4];
            }
#pragma unroll
            for (int ni = 0; ni < 4; ni++) {
                int bb = (n_w + ni * 8 + gid) * PU + ko + tig;
                unsigned bh0 = sWhi[bb], bh1 = sWhi[bb + 4];
                unsigned bl0 = sWlo[bb], bl1 = sWlo[bb + 4];
#pragma unroll
                for (int mi = 0; mi < 2; mi++) {
                    mma_bf16(acc[mi][ni][0], acc[mi][ni][1],
                             acc[mi][ni][2], acc[mi][ni][3],
                             ah[mi][0], ah[mi][1], ah[mi][2], ah[mi][3],
                             bh0, bh1);
                    mma_bf16(acc[mi][ni][0], acc[mi][ni][1],
                             acc[mi][ni][2], acc[mi][ni][3],
                             ah[mi][0], ah[mi][1], ah[mi][2], ah[mi][3],
                             bl0, bl1);
                    mma_bf16(acc[mi][ni][0], acc[mi][ni][1],
                             acc[mi][ni][2], acc[mi][ni][3],
                             al[mi][0], al[mi][1], al[mi][2], al[mi][3],
                             bh0, bh1);
                }
            }
        }
        __syncthreads();
        if (c < 3) {
            STORE_CHUNK();
            __syncthreads();
        }
    }
    #undef LOAD_CHUNK
    #undef STORE_CHUNK

#pragma unroll
    for (int mi = 0; mi < 2; mi++) {
        int ra = row0 + m_w + mi * 16 + gid;
        int rb = ra + 8;
#pragma unroll
        for (int ni = 0; ni < 4; ni++) {
            int col = n_w + ni * 8 + tig * 2;
            *(float2*)&g_xproj[ra * HID + col] =
                make_float2(acc[mi][ni][0], acc[mi][ni][1]);
            *(float2*)&g_xproj[rb * HID + col] =
                make_float2(acc[mi][ni][2], acc[mi][ni][3]);
        }
    }
}

// ======================= recurrent GEMM (fp16 2-pass) =========================
// dst = tanh(xproj + aggr @ wrec), aggr fp16 (g_aggrH), wrec fp16 hi/lo presplit.
// dst_sel: 0 = g_state (+fp16 copy), 2 = dst_ext only
__global__ void __launch_bounds__(256) gemm_rec_kernel(
    int dst_sel, float* __restrict__ dst_ext)
{
    __shared__ unsigned sWhi[HID * PU];
    __shared__ unsigned sWlo[HID * PU];
    __shared__ unsigned sA[GR * PU];

    float* dst = (dst_sel == 2) ? dst_ext : g_state;

    int t = threadIdx.x;
    int lane = t & 31, wid = t >> 5;
    int gid = lane >> 2, tig = lane & 3;
    int wm = wid & 1, wn = wid >> 1;
    int m_w = wm * 32, n_w = wn * 32;
    int row0 = blockIdx.x * GR;

    int wr0 = t >> 2,          wq0 = (t & 3) * 4;
    int wr1 = (t + 256) >> 2,  wq1 = ((t + 256) & 3) * 4;
    int ar  = t >> 2,          aq  = (t & 3) * 4;

    uint4 pwh0, pwh1, pwl0, pwl1, pa;

    #define LOAD_CHUNK(K20) do {                                             \
        pwh0 = *(const uint4*)&g_whi[wr0 * WPK + (K20) + wq0];               \
        pwh1 = *(const uint4*)&g_whi[wr1 * WPK + (K20) + wq1];               \
        pwl0 = *(const uint4*)&g_wlo[wr0 * WPK + (K20) + wq0];               \
        pwl1 = *(const uint4*)&g_wlo[wr1 * WPK + (K20) + wq1];               \
        pa   = *(const uint4*)&g_aggrH[(row0 + ar) * WPK + (K20) + aq];      \
    } while (0)

    #define STORE_CHUNK() do {                                               \
        *(uint4*)&sWhi[wr0 * PU + wq0] = pwh0;                               \
        *(uint4*)&sWhi[wr1 * PU + wq1] = pwh1;                               \
        *(uint4*)&sWlo[wr0 * PU + wq0] = pwl0;                               \
        *(uint4*)&sWlo[wr1 * PU + wq1] = pwl1;                               \
        *(uint4*)&sA[ar * PU + aq] = pa;                                     \
    } while (0)

    float acc[2][4][4];
#pragma unroll
    for (int mi = 0; mi < 2; mi++)
#pragma unroll
        for (int ni = 0; ni < 4; ni++)
#pragma unroll
            for (int q = 0; q < 4; q++) acc[mi][ni][q] = 0.f;

    LOAD_CHUNK(0);
    STORE_CHUNK();
    __syncthreads();

#pragma unroll
    for (int c = 0; c < 4; c++) {
        if (c < 3) LOAD_CHUNK((c + 1) * (KT / 2));

#pragma unroll
        for (int ks = 0; ks < 2; ks++) {
            int ko = ks * 8;
            unsigned ah[2][4];
#pragma unroll
            for (int mi = 0; mi < 2; mi++) {
                int ab = (m_w + mi * 16 + gid) * PU + ko + tig;
                ah[mi][0] = sA[ab];
                ah[mi][1] = sA[ab + 8 * PU];
                ah[mi][2] = sA[ab + 4];
                ah[mi][3] = sA[ab + 8 * PU + 4];
            }
#pragma unroll
            for (int ni = 0; ni < 4; ni++) {
                int bb = (n_w + ni * 8 + gid) * PU + ko + tig;
                unsigned bh0 = sWhi[bb], bh1 = sWhi[bb + 4];
                unsigned bl0 = sWlo[bb], bl1 = sWlo[bb + 4];
#pragma unroll
                for (int mi = 0; mi < 2; mi++) {
                    mma_f16(acc[mi][ni][0], acc[mi][ni][1],
                            acc[mi][ni][2], acc[mi][ni][3],
                            ah[mi][0], ah[mi][1], ah[mi][2], ah[mi][3],
                            bh0, bh1);
                    mma_f16(acc[mi][ni][0], acc[mi][ni][1],
                            acc[mi][ni][2], acc[mi][ni][3],
                            ah[mi][0], ah[mi][1], ah[mi][2], ah[mi][3],
                            bl0, bl1);
                }
            }
        }
        __syncthreads();
        if (c < 3) {
            STORE_CHUNK();
            __syncthreads();
        }
    }
    #undef LOAD_CHUNK
    #undef STORE_CHUNK

#pragma unroll
    for (int mi = 0; mi < 2; mi++) {
        int ra = row0 + m_w + mi * 16 + gid;
        int rb = ra + 8;
#pragma unroll
        for (int ni = 0; ni < 4; ni++) {
            int col = n_w + ni * 8 + tig * 2;
            float2 ba = *(const float2*)&g_xproj[ra * HID + col];
            float2 bb = *(const float2*)&g_xproj[rb * HID + col];
            float v0 = tanhf(acc[mi][ni][0] + ba.x);
            float v1 = tanhf(acc[mi][ni][1] + ba.y);
            float v2 = tanhf(acc[mi][ni][2] + bb.x);
            float v3 = tanhf(acc[mi][ni][3] + bb.y);
            *(float2*)&dst[ra * HID + col] = make_float2(v0, v1);
            *(float2*)&dst[rb * HID + col] = make_float2(v2, v3);
            if (dst_sel == 0) {
                *(__half2*)&g_stateH[ra * HID + col] = __floats2half2_rn(v0, v1);
                *(__half2*)&g_stateH[rb * HID + col] = __floats2half2_rn(v2, v3);
            }
        }
    }
}

// ---------------- host orchestration ----------------
extern "C" void kernel_launch(void* const* d_in, const int* in_sizes, int n_in,
                              void* d_out, int out_size)
{
    const void* ei = nullptr;
    const float* x = nullptr;
    const float* w[4] = {nullptr, nullptr, nullptr, nullptr};
    int wn = 0;
    for (int i = 0; i < n_in; i++) {
        if (in_sizes[i] == 2 * N_EDGES)      ei = d_in[i];
        else if (in_sizes[i] == NH)          x  = (const float*)d_in[i];
        else if (in_sizes[i] == HID * HID && wn < 4) w[wn++] = (const float*)d_in[i];
    }
    const float* w_in0  = w[0];
    const float* w_rec0 = w[1];
    const float* w_in1  = w[2];
    const float* w_rec1 = w[3];
    float* out = (float*)d_out;

    const int BLOCKS = N_NODES / GR;             // 625
    const int TANH_BLOCKS = (NH + 255) / 256;
    const int AGGR_BLOCKS = (N_NODES + 7) / 8;   // 5000
    const int SPLITW_BLOCKS = (HID * WPK + 255) / 256;  // 32

    detect_kernel<<<1, 32>>>(ei);                            // 0
    zero_counts_kernel<<<40, 1024>>>();                      // 1
    split_w_bf16_kernel<<<SPLITW_BLOCKS, 256>>>(w_in0);      // 2
    gemm_proj_kernel<<<BLOCKS, 256>>>(x, 0);                 // 3: xproj = x @ win0^T
    hist_kernel<<<(N_EDGES + 255) / 256, 256>>>(ei);         // 4
    scan_a_kernel<<<NSCB, 256>>>();
    scan_b_kernel<<<1, 256>>>();
    scan_c_kernel<<<NSCB, 256>>>();
    fill_kernel<<<(N_EDGES + 255) / 256, 256>>>(ei);
    tanh_kernel<<<TANH_BLOCKS, 256>>>();                     // state = tanh(xproj)

    for (int layer = 0; layer < 2; layer++) {
        if (layer == 1) {
            split_w_bf16_kernel<<<SPLITW_BLOCKS, 256>>>(w_in1);
            gemm_proj_kernel<<<BLOCKS, 256>>>(nullptr, 1);
            tanh_kernel<<<TANH_BLOCKS, 256>>>();
        }
        const float* wrec = layer ? w_rec1 : w_rec0;
        split_w_f16t_kernel<<<SPLITW_BLOCKS, 256>>>(wrec);

        for (int it = 0; it < 8; it++) {
            aggregate_kernel<<<AGGR_BLOCKS, 256>>>();
            int last = (layer == 1 && it == 7);
            gemm_rec_kernel<<<BLOCKS, 256>>>(last ? 2 : 0, last ? out : nullptr);
        }
    }
}